// round 1
// baseline (speedup 1.0000x reference)
#include <cuda_runtime.h>

#define NPED 6144
#define HID  256
#define OUTD 32

// ---------------- scratch (no allocation allowed) ----------------
__device__ float g_emb [NPED * OUTD];   // neighbour embeddings  [N,32]
__device__ float g_hnew[NPED * HID];    // LSTM hidden output    [N,256]

// ---------------- helpers ----------------
__device__ __forceinline__ bool dless(float d, int j, float dk, int ik) {
    // strict lexicographic (distance, index) — matches top_k tie-break (lower index wins)
    return (d < dk) | ((d == dk) & (j < ik));
}

__device__ __forceinline__ unsigned long long splat2(float x) {
    unsigned long long r; unsigned u = __float_as_uint(x);
    asm("mov.b64 %0, {%1, %1};" : "=l"(r) : "r"(u));
    return r;
}
__device__ __forceinline__ void ffma2(unsigned long long& d,
                                      unsigned long long a,
                                      unsigned long long b) {
    asm("fma.rn.f32x2 %0, %1, %2, %0;" : "+l"(d) : "l"(a), "l"(b));
}
__device__ __forceinline__ float2 unpk(unsigned long long v) {
    unsigned lo, hi;
    asm("mov.b64 {%0, %1}, %2;" : "=r"(lo), "=r"(hi) : "l"(v));
    return make_float2(__uint_as_float(lo), __uint_as_float(hi));
}
__device__ __forceinline__ float sigm(float x) { return 1.f / (1.f + __expf(-x)); }
__device__ __forceinline__ float tanh_f(float x) {
    float xx = fminf(fmaxf(x, -15.f), 15.f);
    float t  = __expf(-2.f * xx);
    return (1.f - t) / (1.f + t);
}

#define TRY_INSERT(dd, jj)                                          \
    if (dless(dd, jj, d3v, i3v)) {                                  \
        if (dless(dd, jj, d2v, i2v)) {                              \
            d3v = d2v; i3v = i2v;                                   \
            if (dless(dd, jj, d1v, i1v)) {                          \
                d2v = d1v; i2v = i1v;                               \
                if (dless(dd, jj, d0v, i0v)) {                      \
                    d1v = d0v; i1v = i0v; d0v = dd; i0v = jj;       \
                } else { d1v = dd; i1v = jj; }                      \
            } else { d2v = dd; i2v = jj; }                          \
        } else { d3v = dd; i3v = jj; }                              \
    }

// =====================================================================
// Kernel A: 4-NN search + neighbour feature embedding
// 192 blocks x 256 threads. Block handles 32 pedestrians (one per lane);
// 8 warps each scan a disjoint 768-wide j-chunk (LDS broadcast: all lanes
// of a warp read the same sPos[j]). Per-thread top-4 in registers, then a
// 32-candidate merge by warp 0.
// =====================================================================
__global__ void __launch_bounds__(256) knn_embed(const float* __restrict__ obs1,
                                                 const float* __restrict__ obs2,
                                                 const float* __restrict__ W_emb,
                                                 const float* __restrict__ b_emb)
{
    extern __shared__ float sm[];
    float2* sPos = (float2*)sm;                     // NPED float2
    float2* sVel = (float2*)(sm + 2 * NPED);        // NPED float2
    float*  sCd  = sm + 4 * NPED;                   // 8*32*4 floats
    int*    sCi  = (int*)(sCd + 8 * 32 * 4);        // 8*32*4 ints
    float*  sW   = (float*)(sCi + 8 * 32 * 4);      // 40 floats (W_emb|b_emb)

    const int tid = threadIdx.x;
    const float2* o2 = (const float2*)obs2;
    const float2* o1 = (const float2*)obs1;
    for (int t = tid; t < NPED; t += 256) {
        float2 p = o2[t], q = o1[t];
        sPos[t] = p;
        sVel[t] = make_float2(p.x - q.x, p.y - q.y);
    }
    if (tid < 40) sW[tid] = (tid < 32) ? W_emb[tid] : b_emb[tid - 32];
    __syncthreads();

    const int li = tid & 31, part = tid >> 5;
    const int i = blockIdx.x * 32 + li;
    const float mx = sPos[i].x, my = sPos[i].y;

    const float INF = __int_as_float(0x7f800000);
    float d0v = INF, d1v = INF, d2v = INF, d3v = INF;
    int   i0v = 0x7fffffff, i1v = 0x7fffffff, i2v = 0x7fffffff, i3v = 0x7fffffff;

    const int jbeg = part * 768, jend = jbeg + 768;
    for (int j = jbeg; j < jend; ++j) {
        float2 o = sPos[j];
        float dx = o.x - mx, dy = o.y - my;
        float dd = dx * dx + dy * dy;
        if (dd <= d3v) {                 // rare path
            if (j != i) { TRY_INSERT(dd, j); }
        }
    }
    {
        int base = (part * 32 + li) * 4;
        sCd[base + 0] = d0v; sCi[base + 0] = i0v;
        sCd[base + 1] = d1v; sCi[base + 1] = i1v;
        sCd[base + 2] = d2v; sCi[base + 2] = i2v;
        sCd[base + 3] = d3v; sCi[base + 3] = i3v;
    }
    __syncthreads();

    if (part == 0) {
        d0v = d1v = d2v = d3v = INF;
        i0v = i1v = i2v = i3v = 0x7fffffff;
        #pragma unroll
        for (int p = 0; p < 8; ++p)
            #pragma unroll
            for (int s = 0; s < 4; ++s) {
                float dd = sCd[(p * 32 + li) * 4 + s];
                int   jj = sCi[(p * 32 + li) * 4 + s];
                TRY_INSERT(dd, jj);
            }

        const float vix = sVel[i].x, viy = sVel[i].y;
        int nb[4] = {i0v, i1v, i2v, i3v};
        #pragma unroll
        for (int k = 0; k < 4; ++k) {
            float2 np = sPos[nb[k]], nv = sVel[nb[k]];
            float px = np.x - mx, py = np.y - my;
            float vx = nv.x - vix, vy = nv.y - viy;
            #pragma unroll
            for (int e = 0; e < 8; ++e) {
                float v = sW[32 + e] + px * sW[e] + py * sW[8 + e]
                        + vx * sW[16 + e] + py * 0.f + vy * sW[24 + e];
                g_emb[i * 32 + k * 8 + e] = fmaxf(v, 0.f);
            }
        }
    }
}

// =====================================================================
// Kernel B: gates = [emb|h] @ [W_ih|W_hh]^T + b, fused LSTM cell -> g_hnew
// Tile: 128 rows (n) x 32 hidden units x 4 gates = 128x128 fp32 tile.
// Tile columns interleaved as ct = jj*4 + gate, so each thread's 4-wide
// accumulator quad holds all four gates of one hidden unit -> register-only
// LSTM epilogue. Inner product uses packed fma.rn.f32x2 (2 MACs/instr).
// Smem tiles are k-major with an XOR-quad swizzle (conflict-free STS + LDS).
// =====================================================================
__global__ void __launch_bounds__(256, 2)
gates_lstm(const float* __restrict__ h, const float* __restrict__ c,
           const float* __restrict__ W_ih, const float* __restrict__ b_ih,
           const float* __restrict__ W_hh, const float* __restrict__ b_hh)
{
    __shared__ float As[32 * 128];
    __shared__ float Bs[32 * 128];
    __shared__ float sbias[128];          // [gate*32 + jj]

    const int tid = threadIdx.x;
    const int n0 = blockIdx.y * 128;
    const int j0 = blockIdx.x * 32;

    if (tid < 128) {
        int g = tid >> 5, jj = tid & 31;
        int row = g * 256 + j0 + jj;
        sbias[tid] = b_ih[row] + b_hh[row];
    }

    const int tx = tid & 15, ty = tid >> 4;

    unsigned long long acc[8][4];
    #pragma unroll
    for (int m = 0; m < 8; ++m)
        #pragma unroll
        for (int p = 0; p < 4; ++p) acc[m][p] = 0ull;

    for (int kc = 0; kc < 9; ++kc) {
        // ---- load A tile: 128 rows x 32 k (emb for kc==0, else h) ----
        #pragma unroll
        for (int it = 0; it < 4; ++it) {
            int l = tid + 256 * it;
            int r = l >> 3, kq = l & 7;
            const float* src = (kc == 0)
                ? (g_emb + (n0 + r) * 32 + kq * 4)
                : (h + (n0 + r) * 256 + (kc - 1) * 32 + kq * 4);
            float4 v = *(const float4*)src;
            int q = (((r >> 2) ^ kq) << 2) + (r & 3);
            As[(kq * 4 + 0) * 128 + q] = v.x;
            As[(kq * 4 + 1) * 128 + q] = v.y;
            As[(kq * 4 + 2) * 128 + q] = v.z;
            As[(kq * 4 + 3) * 128 + q] = v.w;
        }
        // ---- load B tile: 128 interleaved gate-cols x 32 k ----
        #pragma unroll
        for (int it = 0; it < 4; ++it) {
            int l = tid + 256 * it;
            int ct = l >> 3, kq = l & 7;
            int jj = ct >> 2, g = ct & 3;
            int row = g * 256 + j0 + jj;
            const float* src = (kc == 0)
                ? (W_ih + row * 32 + kq * 4)
                : (W_hh + row * 256 + (kc - 1) * 32 + kq * 4);
            float4 v = *(const float4*)src;
            int q = (((ct >> 2) ^ kq) << 2) + (ct & 3);
            Bs[(kq * 4 + 0) * 128 + q] = v.x;
            Bs[(kq * 4 + 1) * 128 + q] = v.y;
            Bs[(kq * 4 + 2) * 128 + q] = v.z;
            Bs[(kq * 4 + 3) * 128 + q] = v.w;
        }
        __syncthreads();

        #pragma unroll
        for (int kk = 0; kk < 32; ++kk) {
            int sw = kk >> 2;
            float4 a0 = *(const float4*)(As + kk * 128 + ((ty ^ sw) << 2));
            float4 a1 = *(const float4*)(As + kk * 128 + (((ty ^ sw) + 16) << 2));
            ulonglong2 b0 = *(const ulonglong2*)(Bs + kk * 128 + ((tx ^ sw) << 2));
            ulonglong2 b1 = *(const ulonglong2*)(Bs + kk * 128 + (((tx ^ sw) + 16) << 2));
            float av[8] = {a0.x, a0.y, a0.z, a0.w, a1.x, a1.y, a1.z, a1.w};
            #pragma unroll
            for (int m = 0; m < 8; ++m) {
                unsigned long long am = splat2(av[m]);
                ffma2(acc[m][0], am, b0.x);
                ffma2(acc[m][1], am, b0.y);
                ffma2(acc[m][2], am, b1.x);
                ffma2(acc[m][3], am, b1.y);
            }
        }
        __syncthreads();
    }

    // ---- LSTM epilogue (register-only, gate order i,f,g,o) ----
    #pragma unroll
    for (int m = 0; m < 8; ++m) {
        int n = n0 + ty * 4 + (m & 3) + ((m >> 2) << 6);
        #pragma unroll
        for (int hf = 0; hf < 2; ++hf) {
            int jj = hf * 16 + tx;
            float2 pif = unpk(acc[m][hf * 2 + 0]);   // (gi, gf)
            float2 pgo = unpk(acc[m][hf * 2 + 1]);   // (gg, go)
            float gi = pif.x + sbias[jj];
            float gf = pif.y + sbias[32 + jj];
            float gg = pgo.x + sbias[64 + jj];
            float go = pgo.y + sbias[96 + jj];
            int j = j0 + jj;
            float cin = c[n * HID + j];
            float cn  = sigm(gf) * cin + sigm(gi) * tanh_f(gg);
            g_hnew[n * HID + j] = sigm(go) * tanh_f(cn);
        }
    }
}

// =====================================================================
// Kernel C: out = h_new @ W_pool^T + b_pool   (6144x32, K=256)
// =====================================================================
__global__ void __launch_bounds__(256) out_gemm(const float* __restrict__ W_pool,
                                                const float* __restrict__ b_pool,
                                                float* __restrict__ out)
{
    __shared__ float hs[64][65];
    __shared__ float ws[64][33];
    const int tid = threadIdx.x;
    const int n0 = blockIdx.x * 64;
    const int nl = tid >> 2, og = (tid & 3) * 8;

    float acc[8];
    #pragma unroll
    for (int u = 0; u < 8; ++u) acc[u] = 0.f;

    for (int kc = 0; kc < 4; ++kc) {
        #pragma unroll
        for (int it = 0; it < 4; ++it) {
            int l = tid + 256 * it;
            int r = l >> 4, kq = l & 15;
            float4 v = *(const float4*)&g_hnew[(n0 + r) * HID + kc * 64 + kq * 4];
            hs[r][kq * 4 + 0] = v.x; hs[r][kq * 4 + 1] = v.y;
            hs[r][kq * 4 + 2] = v.z; hs[r][kq * 4 + 3] = v.w;
        }
        #pragma unroll
        for (int it = 0; it < 2; ++it) {
            int l = tid + 256 * it;
            int o = l >> 4, kq = l & 15;
            float4 v = *(const float4*)&W_pool[o * HID + kc * 64 + kq * 4];
            ws[kq * 4 + 0][o] = v.x; ws[kq * 4 + 1][o] = v.y;
            ws[kq * 4 + 2][o] = v.z; ws[kq * 4 + 3][o] = v.w;
        }
        __syncthreads();
        #pragma unroll 8
        for (int k = 0; k < 64; ++k) {
            float a = hs[nl][k];
            #pragma unroll
            for (int u = 0; u < 8; ++u)
                acc[u] = fmaf(a, ws[k][og + u], acc[u]);
        }
        __syncthreads();
    }
    #pragma unroll
    for (int u = 0; u < 8; ++u)
        out[(n0 + nl) * OUTD + og + u] = acc[u] + b_pool[og + u];
}

// =====================================================================
extern "C" void kernel_launch(void* const* d_in, const int* in_sizes, int n_in,
                              void* d_out, int out_size)
{
    (void)in_sizes; (void)n_in; (void)out_size;
    const float* obs1   = (const float*)d_in[0];
    const float* obs2   = (const float*)d_in[1];
    const float* h      = (const float*)d_in[2];
    const float* c      = (const float*)d_in[3];
    const float* W_emb  = (const float*)d_in[4];
    const float* b_emb  = (const float*)d_in[5];
    const float* W_ih   = (const float*)d_in[6];
    const float* b_ih   = (const float*)d_in[7];
    const float* W_hh   = (const float*)d_in[8];
    const float* b_hh   = (const float*)d_in[9];
    const float* W_pool = (const float*)d_in[10];
    const float* b_pool = (const float*)d_in[11];
    float* out = (float*)d_out;

    size_t smemA = (size_t)(4 * NPED) * 4      // sPos + sVel
                 + (size_t)(8 * 32 * 4) * 4    // sCd
                 + (size_t)(8 * 32 * 4) * 4    // sCi
                 + 40 * 4;                     // sW
    cudaFuncSetAttribute(knn_embed, cudaFuncAttributeMaxDynamicSharedMemorySize,
                         (int)smemA);

    knn_embed<<<NPED / 32, 256, smemA>>>(obs1, obs2, W_emb, b_emb);
    gates_lstm<<<dim3(8, 48), 256>>>(h, c, W_ih, b_ih, W_hh, b_hh);
    out_gemm<<<NPED / 64, 256>>>(W_pool, b_pool, out);
}